// round 2
// baseline (speedup 1.0000x reference)
#include <cuda_runtime.h>
#include <cstdint>

// Problem constants (fixed for this dataset)
#define B_   64
#define D_   256
#define HW_  1024            // 32*32
#define K_   1024            // num embeddings
#define NPIX (B_ * HW_)      // 65536
#define NELM (B_ * D_ * HW_) // 16777216

// Scratch (no cudaMalloc allowed)
__device__ unsigned long long g_best[NPIX];  // packed (orderable_score<<32)|k
__device__ float g_cn[K_];                   // |c_k|^2 (fp32, sequential emulation)
__device__ float g_A[NPIX];                  // |x_n|^2 (fp32, sequential emulation)
__device__ float g_part[B_ * D_];            // per-block loss partials

__device__ __forceinline__ unsigned int float_to_ordered(float f) {
    unsigned int u = __float_as_uint(f);
    return (u & 0x80000000u) ? ~u : (u | 0x80000000u);
}

// ---------------------------------------------------------------------------
// Kernel 0: init g_best
// ---------------------------------------------------------------------------
__global__ void init_best_kernel() {
    int i = blockIdx.x * blockDim.x + threadIdx.x;
    if (i < NPIX) g_best[i] = 0xFFFFFFFFFFFFFFFFull;
}

// ---------------------------------------------------------------------------
// Kernel 1: codebook row norms |c_k|^2 — sequential fp32, mul/add separately
// rounded (emulates XLA CPU strict-fp row reduction). One thread per k.
// ---------------------------------------------------------------------------
__global__ void cn_kernel(const float* __restrict__ C) {
    int k = blockIdx.x * blockDim.x + threadIdx.x;
    if (k >= K_) return;
    const float* row = C + (size_t)k * D_;
    float s = 0.f;
    for (int d = 0; d < D_; d++) {
        float sq = __fmul_rn(row[d], row[d]);
        s = __fadd_rn(s, sq);
    }
    g_cn[k] = s;
}

// ---------------------------------------------------------------------------
// Kernel 1b: per-pixel |x|^2 — sequential fp32 over channels d=0..255
// (NHWC flat order = channel order), mul and add separately rounded.
// One thread per pixel; loads coalesced across pixels.
// ---------------------------------------------------------------------------
__global__ __launch_bounds__(1024)
void a_kernel(const float* __restrict__ X) {
    const int b = blockIdx.x;
    const int p = threadIdx.x;
    const float* Xb = X + (size_t)b * D_ * HW_ + p;
    float s = 0.f;
    #pragma unroll 8
    for (int d = 0; d < D_; d++) {
        float v = Xb[(size_t)d * HW_];
        float sq = __fmul_rn(v, v);
        s = __fadd_rn(s, sq);
    }
    g_A[b * HW_ + p] = s;
}

// ---------------------------------------------------------------------------
// Kernel 2: fused SGEMM + argmin with reference-exact fp32 rounding chain.
// Per batch b: S[k,p] = sum_d C[k,d] * X[b,d,p]
// score = fl32( fl32(A[p] - 2*S) + cn[k] )   (matches jax (T1 - 2T2) + T3)
// Block tile: 128 codes x 128 pixels, 256 threads, 8x8 microtile split
// {t*4..t*4+3, 64+t*4..} for conflict-free LDS.128.
// ---------------------------------------------------------------------------
__global__ __launch_bounds__(256, 2)
void vq_argmin_kernel(const float* __restrict__ X, const float* __restrict__ C) {
    __shared__ union {
        struct { float A[32][128]; float Bt[32][128]; } t;  // A[d][k], Bt[d][p]
        unsigned long long red[128][16];
    } sm;

    const int b     = blockIdx.z;
    const int kBase = blockIdx.y * 128;
    const int pBase = blockIdx.x * 128;
    const int tid   = threadIdx.x;
    const int tx    = tid & 15;   // pixel dim
    const int ty    = tid >> 4;   // code dim

    const float* Xb = X + (size_t)b * D_ * HW_;

    float acc[8][8];
    #pragma unroll
    for (int i = 0; i < 8; i++)
        #pragma unroll
        for (int j = 0; j < 8; j++) acc[i][j] = 0.f;

    for (int dBase = 0; dBase < D_; dBase += 32) {
        #pragma unroll
        for (int i = 0; i < 4; i++) {
            int v   = tid + i * 256;          // 0..1023
            int row = v >> 3;                 // 0..127 (k)
            int c4  = v & 7;                  // 0..7   (d/4)
            float4 f = *reinterpret_cast<const float4*>(
                &C[(size_t)(kBase + row) * D_ + dBase + c4 * 4]);
            sm.t.A[c4 * 4 + 0][row] = f.x;
            sm.t.A[c4 * 4 + 1][row] = f.y;
            sm.t.A[c4 * 4 + 2][row] = f.z;
            sm.t.A[c4 * 4 + 3][row] = f.w;
        }
        #pragma unroll
        for (int i = 0; i < 4; i++) {
            int v   = tid + i * 256;
            int row = v >> 5;                 // 0..31 (d)
            int c4  = v & 31;                 // 0..31 (p/4)
            float4 f = *reinterpret_cast<const float4*>(
                &Xb[(size_t)(dBase + row) * HW_ + pBase + c4 * 4]);
            *reinterpret_cast<float4*>(&sm.t.Bt[row][c4 * 4]) = f;
        }
        __syncthreads();

        #pragma unroll 8
        for (int d = 0; d < 32; d++) {
            float4 a0 = *reinterpret_cast<const float4*>(&sm.t.A[d][ty * 4]);
            float4 a1 = *reinterpret_cast<const float4*>(&sm.t.A[d][64 + ty * 4]);
            float4 b0 = *reinterpret_cast<const float4*>(&sm.t.Bt[d][tx * 4]);
            float4 b1 = *reinterpret_cast<const float4*>(&sm.t.Bt[d][64 + tx * 4]);
            float av[8] = {a0.x, a0.y, a0.z, a0.w, a1.x, a1.y, a1.z, a1.w};
            float bv[8] = {b0.x, b0.y, b0.z, b0.w, b1.x, b1.y, b1.z, b1.w};
            #pragma unroll
            for (int i = 0; i < 8; i++)
                #pragma unroll
                for (int j = 0; j < 8; j++)
                    acc[i][j] = fmaf(av[i], bv[j], acc[i][j]);
        }
        __syncthreads();
    }

    // Epilogue with reference-exact rounding chain.
    int kloc[8], ploc[8];
    #pragma unroll
    for (int i = 0; i < 4; i++) { kloc[i] = ty * 4 + i; kloc[i + 4] = 64 + ty * 4 + i; }
    #pragma unroll
    for (int j = 0; j < 4; j++) { ploc[j] = tx * 4 + j; ploc[j + 4] = 64 + tx * 4 + j; }

    float cnv[8], Av[8];
    #pragma unroll
    for (int i = 0; i < 8; i++) cnv[i] = g_cn[kBase + kloc[i]];
    #pragma unroll
    for (int j = 0; j < 8; j++) Av[j] = g_A[b * HW_ + pBase + ploc[j]];

    unsigned long long keys[8];
    #pragma unroll
    for (int j = 0; j < 8; j++) {
        // score(i) = fl( fl(A - 2*dot) + cn )  — explicit rounded ops, no FMA
        float m2d0  = __fmul_rn(-2.0f, acc[0][j]);
        float u0    = __fadd_rn(Av[j], m2d0);
        float best  = __fadd_rn(u0, cnv[0]);
        int   bk    = kBase + kloc[0];
        #pragma unroll
        for (int i = 1; i < 8; i++) {
            float m2d = __fmul_rn(-2.0f, acc[i][j]);
            float u   = __fadd_rn(Av[j], m2d);
            float v   = __fadd_rn(u, cnv[i]);
            if (v < best) { best = v; bk = kBase + kloc[i]; }  // ascending k: ties keep low k
        }
        keys[j] = ((unsigned long long)float_to_ordered(best) << 32) |
                  (unsigned long long)(unsigned int)bk;
    }

    __syncthreads();   // smem reuse as reduce buffer
    #pragma unroll
    for (int j = 0; j < 8; j++) sm.red[ploc[j]][ty] = keys[j];
    __syncthreads();

    if (tid < 128) {
        unsigned long long m = sm.red[tid][0];
        #pragma unroll
        for (int t = 1; t < 16; t++) {
            unsigned long long v = sm.red[tid][t];
            m = (v < m) ? v : m;
        }
        atomicMin(&g_best[b * HW_ + pBase + tid], m);
    }
}

// ---------------------------------------------------------------------------
// Kernel 3: gather output (NCHW) + per-block loss partial sums.
// ---------------------------------------------------------------------------
__global__ __launch_bounds__(256)
void gather_kernel(const float* __restrict__ X, const float* __restrict__ C,
                   float* __restrict__ out) {
    __shared__ float red[8];
    const int bd = blockIdx.x;
    const int b  = bd >> 8;
    const int d  = bd & 255;
    const int p  = threadIdx.x * 4;

    const unsigned long long* __restrict__ best = &g_best[b * HW_];
    const size_t base = ((size_t)b * D_ + d) * HW_ + p;

    float4 x = *reinterpret_cast<const float4*>(&X[base]);
    float q[4];
    #pragma unroll
    for (int j = 0; j < 4; j++) {
        int k = (int)(unsigned int)(best[p + j] & 0xFFFFFFFFull);
        q[j] = C[(size_t)k * D_ + d];
    }
    float4 qo = make_float4(q[0], q[1], q[2], q[3]);
    *reinterpret_cast<float4*>(&out[base]) = qo;

    float dx0 = q[0] - x.x, dx1 = q[1] - x.y, dx2 = q[2] - x.z, dx3 = q[3] - x.w;
    float s = dx0 * dx0 + dx1 * dx1 + dx2 * dx2 + dx3 * dx3;

    #pragma unroll
    for (int o = 16; o > 0; o >>= 1) s += __shfl_down_sync(0xFFFFFFFFu, s, o);
    int warp = threadIdx.x >> 5;
    if ((threadIdx.x & 31) == 0) red[warp] = s;
    __syncthreads();
    if (threadIdx.x == 0) {
        float t = 0.f;
        #pragma unroll
        for (int w = 0; w < 8; w++) t += red[w];
        g_part[bd] = t;
    }
}

// ---------------------------------------------------------------------------
// Kernel 4: final loss reduction (deterministic, double accumulate)
// ---------------------------------------------------------------------------
__global__ void finalize_kernel(float* __restrict__ out, int loss_idx) {
    __shared__ double red[256];
    double s = 0.0;
    for (int i = threadIdx.x; i < B_ * D_; i += 256) s += (double)g_part[i];
    red[threadIdx.x] = s;
    __syncthreads();
    for (int o = 128; o > 0; o >>= 1) {
        if (threadIdx.x < o) red[threadIdx.x] += red[threadIdx.x + o];
        __syncthreads();
    }
    if (threadIdx.x == 0) {
        double mse = red[0] / (double)NELM;
        out[loss_idx] = (float)(1.25 * mse);   // quantization + 0.25*encoding
    }
}

// ---------------------------------------------------------------------------
extern "C" void kernel_launch(void* const* d_in, const int* in_sizes, int n_in,
                              void* d_out, int out_size) {
    const float* X = (const float*)d_in[0];   // inputs [64,256,32,32] f32
    const float* C = (const float*)d_in[1];   // codebook [1024,256] f32
    float* out = (float*)d_out;

    init_best_kernel<<<NPIX / 256, 256>>>();
    cn_kernel<<<K_ / 256, 256>>>(C);
    a_kernel<<<B_, 1024>>>(X);

    dim3 grid(HW_ / 128, K_ / 128, B_);       // (8, 8, 64)
    vq_argmin_kernel<<<grid, 256>>>(X, C);

    gather_kernel<<<B_ * D_, 256>>>(X, C, out);

    if (out_size > NELM) {
        finalize_kernel<<<1, 256>>>(out, out_size - 1);
    }
}

// round 4
// speedup vs baseline: 1.0519x; 1.0519x over previous
#include <cuda_runtime.h>
#include <cuda_bf16.h>
#include <cstdint>

// Problem constants (fixed for this dataset)
#define B_   64
#define D_   256
#define HW_  1024            // 32*32
#define K_   1024            // num embeddings
#define NPIX (B_ * HW_)      // 65536
#define NELM (B_ * D_ * HW_) // 16777216
#define CAND_CAP 4194304
#define EPS_MARGIN 5e-3f

// ---------------------------------------------------------------------------
// Scratch (device globals; no cudaMalloc allowed)
// ---------------------------------------------------------------------------
__device__ unsigned long long g_best[NPIX];   // packed (orderable_score<<32)|k
__device__ float g_cn[K_];                    // |c_k|^2 (exact sequential chain)
__device__ float g_A[NPIX];                   // |x_n|^2 (exact sequential chain)
__device__ float g_part[B_ * D_];             // loss partials
__device__ float g_Xt[NPIX * D_];             // X transposed: [pix][d] fp32
__device__ __nv_bfloat16 g_Xt_bf[NPIX * D_];  // bf16 copy
__device__ __nv_bfloat16 g_Cbf[K_ * D_];      // codebook bf16
__device__ unsigned long long g_cand[CAND_CAP]; // (bf16score_bits<<32)|(pix<<10)|k
__device__ unsigned int g_ncand;
__device__ float g_tilemin[NPIX * 8];         // per (pixel, k-tile) bf16-score min
__device__ float g_gmin[NPIX];                // per pixel global bf16-score min

__device__ __forceinline__ unsigned int float_to_ordered(float f) {
    unsigned int u = __float_as_uint(f);
    return (u & 0x80000000u) ? ~u : (u | 0x80000000u);
}

__device__ __forceinline__ uint32_t smem_u32(const void* p) {
    uint32_t a;
    asm("{ .reg .u64 t; cvta.to.shared.u64 t, %1; cvt.u32.u64 %0, t; }"
        : "=r"(a) : "l"(p));
    return a;
}

// cp.async 16B (sm_80+, legal on plain sm_103 target)
__device__ __forceinline__ void cp16(uint32_t saddr, const void* g) {
    asm volatile("cp.async.cg.shared.global [%0], [%1], 16;"
                 :: "r"(saddr), "l"(g) : "memory");
}

// ldmatrix x4 (non-transposed, b16)
__device__ __forceinline__ void ldm_x4(uint32_t* r, uint32_t addr) {
    asm volatile("ldmatrix.sync.aligned.m8n8.x4.shared.b16 {%0,%1,%2,%3}, [%4];"
                 : "=r"(r[0]), "=r"(r[1]), "=r"(r[2]), "=r"(r[3]) : "r"(addr));
}

// bf16 HMMA m16n8k16, f32 accumulate (sm_80+)
__device__ __forceinline__ void mma_bf16(float* c, const uint32_t* a,
                                         uint32_t b0, uint32_t b1) {
    asm volatile(
        "mma.sync.aligned.m16n8k16.row.col.f32.bf16.bf16.f32 "
        "{%0,%1,%2,%3}, {%4,%5,%6,%7}, {%8,%9}, {%0,%1,%2,%3};"
        : "+f"(c[0]), "+f"(c[1]), "+f"(c[2]), "+f"(c[3])
        : "r"(a[0]), "r"(a[1]), "r"(a[2]), "r"(a[3]), "r"(b0), "r"(b1));
}

// ---------------------------------------------------------------------------
// Kernel 0: init g_best + candidate counter
// ---------------------------------------------------------------------------
__global__ void init_kernel() {
    int i = blockIdx.x * blockDim.x + threadIdx.x;
    if (i < NPIX) g_best[i] = 0xFFFFFFFFFFFFFFFFull;
    if (i == 0) g_ncand = 0;
}

// ---------------------------------------------------------------------------
// Kernel 1: |c_k|^2, exact sequential fp32 chain (validated Round 2)
// ---------------------------------------------------------------------------
__global__ void cn_kernel(const float* __restrict__ C) {
    int k = blockIdx.x * blockDim.x + threadIdx.x;
    if (k >= K_) return;
    const float* row = C + (size_t)k * D_;
    float s = 0.f;
    for (int d = 0; d < D_; d++) s = __fadd_rn(s, __fmul_rn(row[d], row[d]));
    g_cn[k] = s;
}

// ---------------------------------------------------------------------------
// Kernel 1b: |x_p|^2, exact sequential fp32 chain (validated Round 2)
// ---------------------------------------------------------------------------
__global__ __launch_bounds__(1024)
void a_kernel(const float* __restrict__ X) {
    const int b = blockIdx.x;
    const int p = threadIdx.x;
    const float* Xb = X + (size_t)b * D_ * HW_ + p;
    float s = 0.f;
    #pragma unroll 8
    for (int d = 0; d < D_; d++) {
        float v = Xb[(size_t)d * HW_];
        s = __fadd_rn(s, __fmul_rn(v, v));
    }
    g_A[b * HW_ + p] = s;
}

// ---------------------------------------------------------------------------
// Kernel 1c: codebook -> bf16
// ---------------------------------------------------------------------------
__global__ void cbf_kernel(const float* __restrict__ C) {
    int i = blockIdx.x * blockDim.x + threadIdx.x;
    if (i < K_ * D_) g_Cbf[i] = __float2bfloat16(C[i]);
}

// ---------------------------------------------------------------------------
// Kernel 1d: transpose X NCHW [b][d][p] -> pixel-major [pix][d], f32+bf16
// ---------------------------------------------------------------------------
__global__ __launch_bounds__(256)
void transpose_kernel(const float* __restrict__ X) {
    __shared__ float t[32][33];
    const int b  = blockIdx.z;
    const int dB = blockIdx.y * 32;
    const int pB = blockIdx.x * 32;
    const int tx = threadIdx.x;       // 0..31
    const int ty = threadIdx.y;       // 0..7

    const float* src = X + ((size_t)b * D_ + dB) * HW_ + pB;
    #pragma unroll
    for (int i = 0; i < 32; i += 8)
        t[ty + i][tx] = src[(size_t)(ty + i) * HW_ + tx];
    __syncthreads();

    const size_t obase = ((size_t)(b * HW_ + pB)) * D_ + dB;
    #pragma unroll
    for (int i = 0; i < 32; i += 8) {
        int row = ty + i;
        float v = t[tx][row];
        g_Xt[obase + (size_t)row * D_ + tx] = v;
        g_Xt_bf[obase + (size_t)row * D_ + tx] = __float2bfloat16(v);
    }
}

// ---------------------------------------------------------------------------
// Kernel 2: bf16 HMMA GEMM (128 pixels x 128 codes x K=256) + candidate filter.
// A = Xt_bf rows (pixels), B = Cbf rows (codes), both K-major in gmem.
// SMEM rows of 512B with 16B-chunk XOR swizzle: off = r*512 + (kb ^ ((r&7)<<4)).
// 8 warps: warp (m,n) = (wid&1, wid>>2? no: wid>>1) -> 64x32 tile each.
// Epilogue: scores = cn - 2*S into smem (stride 132), per-pixel tile min,
// candidates within min+EPS pushed with their bf16 score for later gating.
// ---------------------------------------------------------------------------
__global__ __launch_bounds__(256, 1)
void vq_mma_kernel() {
    extern __shared__ char dsm_raw[];
    __shared__ float s_cn[128];

    const int tid = threadIdx.x, lane = tid & 31, wid = tid >> 5;
    const int pt = blockIdx.x;   // 0..511 pixel tiles (128 pixels each)
    const int kt = blockIdx.y;   // 0..7 code tiles (128 codes each)

    const uint32_t s0 = smem_u32(dsm_raw);
    const uint32_t base = (s0 + 1023) & ~1023u;
    const uint32_t sA = base, sB = base + 65536;
    float* scores = reinterpret_cast<float*>(dsm_raw + (base - s0));

    if (tid < 128) s_cn[tid] = g_cn[kt * 128 + tid];

    // Stage operands: 64KB each, cp.async 16B chunks (32 chunks per 512B row)
    const __nv_bfloat16* gA = g_Xt_bf + (size_t)pt * 128 * D_;
    const __nv_bfloat16* gB = g_Cbf + (size_t)kt * 128 * D_;
    #pragma unroll
    for (int i = 0; i < 16; i++) {
        int v = i * 256 + tid;             // 0..4095
        int r = v >> 5, c = v & 31;
        uint32_t off = (uint32_t)(r * 512) + (((uint32_t)c * 16) ^ ((uint32_t)(r & 7) << 4));
        cp16(sA + off, gA + (size_t)v * 8);
        cp16(sB + off, gB + (size_t)v * 8);
    }
    asm volatile("cp.async.commit_group;");
    asm volatile("cp.async.wait_group 0;" ::: "memory");
    __syncthreads();

    // Warp tiling: 2 (m) x 4 (n)
    const int wm = (wid & 1) * 64;
    const int wn = (wid >> 1) * 32;
    // ldmatrix lane address maps
    const int a_row = wm + (lane & 15);
    const uint32_t a_swz = (uint32_t)((a_row & 7) << 4);
    const int a_kb = (lane >> 4) * 16;
    const int b_row = wn + ((lane & 7) | ((lane & 16) >> 1));
    const uint32_t b_swz = (uint32_t)((b_row & 7) << 4);
    const int b_kb = ((lane >> 3) & 1) * 16;

    float acc[4][4][4];
    #pragma unroll
    for (int mi = 0; mi < 4; mi++)
        #pragma unroll
        for (int nt = 0; nt < 4; nt++)
            #pragma unroll
            for (int e = 0; e < 4; e++) acc[mi][nt][e] = 0.f;

    #pragma unroll
    for (int ks = 0; ks < 16; ks++) {
        uint32_t af[4][4], bf[2][4];
        #pragma unroll
        for (int mi = 0; mi < 4; mi++)
            ldm_x4(af[mi], sA + (uint32_t)(a_row + mi * 16) * 512 +
                           (((uint32_t)(ks * 32 + a_kb)) ^ a_swz));
        #pragma unroll
        for (int nj = 0; nj < 2; nj++)
            ldm_x4(bf[nj], sB + (uint32_t)(b_row + nj * 16) * 512 +
                           (((uint32_t)(ks * 32 + b_kb)) ^ b_swz));
        #pragma unroll
        for (int mi = 0; mi < 4; mi++)
            #pragma unroll
            for (int nt = 0; nt < 4; nt++)
                mma_bf16(acc[mi][nt], af[mi],
                         bf[nt >> 1][(nt & 1) * 2], bf[nt >> 1][(nt & 1) * 2 + 1]);
    }

    __syncthreads();   // everyone done reading operands; reuse smem for scores

    // Scores: sc = cn[k] - 2*S; smem layout [128][132] f32 (stride 132)
    #pragma unroll
    for (int mi = 0; mi < 4; mi++) {
        int r0 = wm + mi * 16 + (lane >> 2);
        #pragma unroll
        for (int nt = 0; nt < 4; nt++) {
            int c0 = wn + nt * 8 + (lane & 3) * 2;
            float cn0 = s_cn[c0], cn1 = s_cn[c0 + 1];
            scores[r0 * 132 + c0]           = fmaf(-2.f, acc[mi][nt][0], cn0);
            scores[r0 * 132 + c0 + 1]       = fmaf(-2.f, acc[mi][nt][1], cn1);
            scores[(r0 + 8) * 132 + c0]     = fmaf(-2.f, acc[mi][nt][2], cn0);
            scores[(r0 + 8) * 132 + c0 + 1] = fmaf(-2.f, acc[mi][nt][3], cn1);
        }
    }
    __syncthreads();

    // Scan: 2 threads per pixel row (64 codes each)
    const int row = tid >> 1, half = tid & 1;
    const float* sr = scores + row * 132 + half * 64;
    float best = 3.4e38f;
    #pragma unroll
    for (int q = 0; q < 16; q++) {
        float4 v = *reinterpret_cast<const float4*>(sr + q * 4);
        best = fminf(best, fminf(fminf(v.x, v.y), fminf(v.z, v.w)));
    }
    float ob = __shfl_xor_sync(0xFFFFFFFFu, best, 1);
    best = fminf(best, ob);
    const unsigned pix = (unsigned)(pt * 128 + row);
    if (half == 0) g_tilemin[pix * 8 + kt] = best;
    const float thr = best + EPS_MARGIN;

    // Candidate push (warp-aggregated atomics), score carried for gating
    for (int j = 0; j < 64; j++) {
        float sc = sr[j];
        bool pred = (sc <= thr);
        unsigned mask = __ballot_sync(0xFFFFFFFFu, pred);
        if (mask) {
            int leader = __ffs(mask) - 1;
            unsigned bidx = 0;
            if (lane == leader) bidx = atomicAdd(&g_ncand, (unsigned)__popc(mask));
            bidx = __shfl_sync(0xFFFFFFFFu, bidx, leader);
            if (pred) {
                unsigned slot = bidx + __popc(mask & ((1u << lane) - 1u));
                unsigned k = (unsigned)(kt * 128 + half * 64 + j);
                if (slot < CAND_CAP)
                    g_cand[slot] = ((unsigned long long)__float_as_uint(sc) << 32) |
                                   ((unsigned long long)pix << 10) | k;
            }
        }
    }
}

// ---------------------------------------------------------------------------
// Kernel 2b: per-pixel global min of the 8 tile minima
// ---------------------------------------------------------------------------
__global__ void gmin_kernel() {
    int p = blockIdx.x * blockDim.x + threadIdx.x;
    if (p >= NPIX) return;
    float m = 3.4e38f;
    #pragma unroll
    for (int t = 0; t < 8; t++) m = fminf(m, g_tilemin[p * 8 + t]);
    g_gmin[p] = m;
}

// ---------------------------------------------------------------------------
// Kernel 3: exact fp32 rescore of gated candidates (one warp each).
// Gate: candidate's bf16 score must be within EPS of the pixel's global
// bf16 min (provably keeps the true argmin; skips ~85% of candidates).
// score = fl(fl(A - 2*dot) + cn)  — the Round-2-validated rounding chain.
// ---------------------------------------------------------------------------
__global__ __launch_bounds__(256)
void rescore_kernel(const float* __restrict__ C) {
    const unsigned int count = min(g_ncand, (unsigned)CAND_CAP);
    const int lane = threadIdx.x & 31;
    const unsigned gw = (blockIdx.x * blockDim.x + threadIdx.x) >> 5;
    const unsigned nw = (gridDim.x * blockDim.x) >> 5;

    for (unsigned i = gw; i < count; i += nw) {
        unsigned long long e = g_cand[i];
        float sc_bf = __uint_as_float((unsigned)(e >> 32));
        unsigned low = (unsigned)e;
        unsigned pix = low >> 10, k = low & 1023u;
        if (sc_bf > g_gmin[pix] + EPS_MARGIN) continue;

        const float4* xr = reinterpret_cast<const float4*>(g_Xt + (size_t)pix * D_);
        const float4* cr = reinterpret_cast<const float4*>(C + (size_t)k * D_);
        float dot = 0.f;
        #pragma unroll
        for (int t = 0; t < 2; t++) {
            float4 xv = xr[lane * 2 + t];
            float4 cv = cr[lane * 2 + t];
            dot = fmaf(xv.x, cv.x, dot);
            dot = fmaf(xv.y, cv.y, dot);
            dot = fmaf(xv.z, cv.z, dot);
            dot = fmaf(xv.w, cv.w, dot);
        }
        #pragma unroll
        for (int o = 16; o > 0; o >>= 1) dot += __shfl_down_sync(0xFFFFFFFFu, dot, o);
        if (lane == 0) {
            float sc = __fadd_rn(__fadd_rn(g_A[pix], __fmul_rn(-2.0f, dot)), g_cn[k]);
            unsigned long long key =
                ((unsigned long long)float_to_ordered(sc) << 32) | (unsigned long long)k;
            atomicMin(&g_best[pix], key);
        }
    }
}

// ---------------------------------------------------------------------------
// Kernel 4: gather output (NCHW) + per-block loss partial sums.
// ---------------------------------------------------------------------------
__global__ __launch_bounds__(256)
void gather_kernel(const float* __restrict__ X, const float* __restrict__ C,
                   float* __restrict__ out) {
    __shared__ float red[8];
    const int bd = blockIdx.x;
    const int b  = bd >> 8;
    const int d  = bd & 255;
    const int p  = threadIdx.x * 4;

    const unsigned long long* __restrict__ best = &g_best[b * HW_];
    const size_t base = ((size_t)b * D_ + d) * HW_ + p;

    float4 x = *reinterpret_cast<const float4*>(&X[base]);
    float q[4];
    #pragma unroll
    for (int j = 0; j < 4; j++) {
        int k = (int)(unsigned int)(best[p + j] & 0xFFFFFFFFull);
        q[j] = C[(size_t)k * D_ + d];
    }
    *reinterpret_cast<float4*>(&out[base]) = make_float4(q[0], q[1], q[2], q[3]);

    float dx0 = q[0] - x.x, dx1 = q[1] - x.y, dx2 = q[2] - x.z, dx3 = q[3] - x.w;
    float s = dx0 * dx0 + dx1 * dx1 + dx2 * dx2 + dx3 * dx3;
    #pragma unroll
    for (int o = 16; o > 0; o >>= 1) s += __shfl_down_sync(0xFFFFFFFFu, s, o);
    int warp = threadIdx.x >> 5;
    if ((threadIdx.x & 31) == 0) red[warp] = s;
    __syncthreads();
    if (threadIdx.x == 0) {
        float t = 0.f;
        #pragma unroll
        for (int w = 0; w < 8; w++) t += red[w];
        g_part[bd] = t;
    }
}

// ---------------------------------------------------------------------------
// Kernel 5: final loss reduction
// ---------------------------------------------------------------------------
__global__ void finalize_kernel(float* __restrict__ out, int loss_idx) {
    __shared__ double red[256];
    double s = 0.0;
    for (int i = threadIdx.x; i < B_ * D_; i += 256) s += (double)g_part[i];
    red[threadIdx.x] = s;
    __syncthreads();
    for (int o = 128; o > 0; o >>= 1) {
        if (threadIdx.x < o) red[threadIdx.x] += red[threadIdx.x + o];
        __syncthreads();
    }
    if (threadIdx.x == 0) {
        double mse = red[0] / (double)NELM;
        out[loss_idx] = (float)(1.25 * mse);
    }
}

// ---------------------------------------------------------------------------
extern "C" void kernel_launch(void* const* d_in, const int* in_sizes, int n_in,
                              void* d_out, int out_size) {
    const float* X = (const float*)d_in[0];   // [64,256,32,32] f32 NCHW
    const float* C = (const float*)d_in[1];   // [1024,256] f32
    float* out = (float*)d_out;

    static const int SMEM_BYTES = 131072 + 1024;   // A/B tiles (+ align slack)
    cudaFuncSetAttribute(vq_mma_kernel,
                         cudaFuncAttributeMaxDynamicSharedMemorySize, SMEM_BYTES);

    init_kernel<<<NPIX / 256, 256>>>();
    cn_kernel<<<K_ / 256, 256>>>(C);
    a_kernel<<<B_, 1024>>>(X);
    cbf_kernel<<<(K_ * D_) / 1024, 1024>>>(C);
    transpose_kernel<<<dim3(HW_ / 32, D_ / 32, B_), dim3(32, 8)>>>(X);

    vq_mma_kernel<<<dim3(NPIX / 128, K_ / 128), 256, SMEM_BYTES>>>();

    gmin_kernel<<<NPIX / 256, 256>>>();
    rescore_kernel<<<2048, 256>>>(C);

    gather_kernel<<<B_ * D_, 256>>>(X, C, out);

    if (out_size > NELM) {
        finalize_kernel<<<1, 256>>>(out, out_size - 1);
    }
}

// round 5
// speedup vs baseline: 1.5210x; 1.4460x over previous
#include <cuda_runtime.h>
#include <cuda_bf16.h>
#include <cstdint>

// Problem constants (fixed for this dataset)
#define B_   64
#define D_   256
#define HW_  1024            // 32*32
#define K_   1024            // num embeddings
#define NPIX (B_ * HW_)      // 65536
#define NELM (B_ * D_ * HW_) // 16777216
#define CAND_CAP 4194304
#define EPS_MARGIN 5e-3f
#define STAGE_CAP 7680

// ---------------------------------------------------------------------------
// Scratch (device globals; no cudaMalloc allowed)
// ---------------------------------------------------------------------------
__device__ unsigned long long g_best[NPIX];   // packed (orderable_score<<32)|k
__device__ float g_cn[K_];                    // |c_k|^2 (exact sequential chain)
__device__ float g_A[NPIX];                   // |x_n|^2 (exact sequential chain)
__device__ float g_part[B_ * D_];             // loss partials
__device__ float g_Xt[NPIX * D_];             // X transposed: [pix][d] fp32
__device__ __nv_bfloat16 g_Xt_bf[NPIX * D_];  // bf16 copy
__device__ __nv_bfloat16 g_Cbf[K_ * D_];      // codebook bf16
__device__ unsigned long long g_cand[CAND_CAP]; // (bf16score_bits<<32)|(pix<<10)|k
__device__ unsigned int g_ncand;
__device__ float g_tilemin[NPIX * 8];         // per (pixel, k-tile) bf16-score min
__device__ float g_gmin[NPIX];                // per pixel global bf16-score min

__device__ __forceinline__ unsigned int float_to_ordered(float f) {
    unsigned int u = __float_as_uint(f);
    return (u & 0x80000000u) ? ~u : (u | 0x80000000u);
}

__device__ __forceinline__ uint32_t smem_u32(const void* p) {
    uint32_t a;
    asm("{ .reg .u64 t; cvta.to.shared.u64 t, %1; cvt.u32.u64 %0, t; }"
        : "=r"(a) : "l"(p));
    return a;
}

// cp.async 16B (sm_80+, legal on plain sm_103 target)
__device__ __forceinline__ void cp16(uint32_t saddr, const void* g) {
    asm volatile("cp.async.cg.shared.global [%0], [%1], 16;"
                 :: "r"(saddr), "l"(g) : "memory");
}

// ldmatrix x4 (non-transposed, b16)
__device__ __forceinline__ void ldm_x4(uint32_t* r, uint32_t addr) {
    asm volatile("ldmatrix.sync.aligned.m8n8.x4.shared.b16 {%0,%1,%2,%3}, [%4];"
                 : "=r"(r[0]), "=r"(r[1]), "=r"(r[2]), "=r"(r[3]) : "r"(addr));
}

// bf16 HMMA m16n8k16, f32 accumulate (sm_80+)
__device__ __forceinline__ void mma_bf16(float* c, const uint32_t* a,
                                         uint32_t b0, uint32_t b1) {
    asm volatile(
        "mma.sync.aligned.m16n8k16.row.col.f32.bf16.bf16.f32 "
        "{%0,%1,%2,%3}, {%4,%5,%6,%7}, {%8,%9}, {%0,%1,%2,%3};"
        : "+f"(c[0]), "+f"(c[1]), "+f"(c[2]), "+f"(c[3])
        : "r"(a[0]), "r"(a[1]), "r"(a[2]), "r"(a[3]), "r"(b0), "r"(b1));
}

// ---------------------------------------------------------------------------
// Kernel 0: init g_best + candidate counter
// ---------------------------------------------------------------------------
__global__ void init_kernel() {
    int i = blockIdx.x * blockDim.x + threadIdx.x;
    if (i < NPIX) g_best[i] = 0xFFFFFFFFFFFFFFFFull;
    if (i == 0) g_ncand = 0;
}

// ---------------------------------------------------------------------------
// Kernel 1: |c_k|^2, exact sequential fp32 chain (validated Round 2)
// ---------------------------------------------------------------------------
__global__ void cn_kernel(const float* __restrict__ C) {
    int k = blockIdx.x * blockDim.x + threadIdx.x;
    if (k >= K_) return;
    const float* row = C + (size_t)k * D_;
    float s = 0.f;
    for (int d = 0; d < D_; d++) s = __fadd_rn(s, __fmul_rn(row[d], row[d]));
    g_cn[k] = s;
}

// ---------------------------------------------------------------------------
// Kernel 1b: |x_p|^2, exact sequential fp32 chain (validated Round 2)
// ---------------------------------------------------------------------------
__global__ __launch_bounds__(1024)
void a_kernel(const float* __restrict__ X) {
    const int b = blockIdx.x;
    const int p = threadIdx.x;
    const float* Xb = X + (size_t)b * D_ * HW_ + p;
    float s = 0.f;
    #pragma unroll 8
    for (int d = 0; d < D_; d++) {
        float v = Xb[(size_t)d * HW_];
        s = __fadd_rn(s, __fmul_rn(v, v));
    }
    g_A[b * HW_ + p] = s;
}

// ---------------------------------------------------------------------------
// Kernel 1c: codebook -> bf16
// ---------------------------------------------------------------------------
__global__ void cbf_kernel(const float* __restrict__ C) {
    int i = blockIdx.x * blockDim.x + threadIdx.x;
    if (i < K_ * D_) g_Cbf[i] = __float2bfloat16(C[i]);
}

// ---------------------------------------------------------------------------
// Kernel 1d: transpose X NCHW [b][d][p] -> pixel-major [pix][d], f32+bf16
// ---------------------------------------------------------------------------
__global__ __launch_bounds__(256)
void transpose_kernel(const float* __restrict__ X) {
    __shared__ float t[32][33];
    const int b  = blockIdx.z;
    const int dB = blockIdx.y * 32;
    const int pB = blockIdx.x * 32;
    const int tx = threadIdx.x;       // 0..31
    const int ty = threadIdx.y;       // 0..7

    const float* src = X + ((size_t)b * D_ + dB) * HW_ + pB;
    #pragma unroll
    for (int i = 0; i < 32; i += 8)
        t[ty + i][tx] = src[(size_t)(ty + i) * HW_ + tx];
    __syncthreads();

    const size_t obase = ((size_t)(b * HW_ + pB)) * D_ + dB;
    #pragma unroll
    for (int i = 0; i < 32; i += 8) {
        int row = ty + i;
        float v = t[tx][row];
        g_Xt[obase + (size_t)row * D_ + tx] = v;
        g_Xt_bf[obase + (size_t)row * D_ + tx] = __float2bfloat16(v);
    }
}

// ---------------------------------------------------------------------------
// Kernel 2: bf16 HMMA GEMM (128 pixels x 128 codes x K=256) + candidate filter.
// Candidate emission is BLOCK-AGGREGATED: warp-level ballots bump a SMEM
// counter (ATOMS), entries staged in smem, then ONE global atomicAdd per CTA
// and a coalesced flush — removes the single-address global atomic hotspot.
// ---------------------------------------------------------------------------
__global__ __launch_bounds__(256, 1)
void vq_mma_kernel() {
    extern __shared__ char dsm_raw[];
    __shared__ float s_cn[128];
    __shared__ unsigned int s_cnt, s_base;

    const int tid = threadIdx.x, lane = tid & 31, wid = tid >> 5;
    const int pt = blockIdx.x;   // 0..511 pixel tiles (128 pixels each)
    const int kt = blockIdx.y;   // 0..7 code tiles (128 codes each)

    const uint32_t s0 = smem_u32(dsm_raw);
    const uint32_t base = (s0 + 1023) & ~1023u;
    const uint32_t sA = base, sB = base + 65536;
    char* dyn = dsm_raw + (base - s0);
    float* scores = reinterpret_cast<float*>(dyn);                 // [128][132] f32 (67584B)
    unsigned long long* stage =
        reinterpret_cast<unsigned long long*>(dyn + 68608);        // 7680 u64 (61440B)

    if (tid < 128) s_cn[tid] = g_cn[kt * 128 + tid];
    if (tid == 0) s_cnt = 0;

    // Stage operands: 64KB each, cp.async 16B chunks (32 chunks per 512B row)
    const __nv_bfloat16* gA = g_Xt_bf + (size_t)pt * 128 * D_;
    const __nv_bfloat16* gB = g_Cbf + (size_t)kt * 128 * D_;
    #pragma unroll
    for (int i = 0; i < 16; i++) {
        int v = i * 256 + tid;             // 0..4095
        int r = v >> 5, c = v & 31;
        uint32_t off = (uint32_t)(r * 512) + (((uint32_t)c * 16) ^ ((uint32_t)(r & 7) << 4));
        cp16(sA + off, gA + (size_t)v * 8);
        cp16(sB + off, gB + (size_t)v * 8);
    }
    asm volatile("cp.async.commit_group;");
    asm volatile("cp.async.wait_group 0;" ::: "memory");
    __syncthreads();

    // Warp tiling: 2 (m) x 4 (n)
    const int wm = (wid & 1) * 64;
    const int wn = (wid >> 1) * 32;
    const int a_row = wm + (lane & 15);
    const uint32_t a_swz = (uint32_t)((a_row & 7) << 4);
    const int a_kb = (lane >> 4) * 16;
    const int b_row = wn + ((lane & 7) | ((lane & 16) >> 1));
    const uint32_t b_swz = (uint32_t)((b_row & 7) << 4);
    const int b_kb = ((lane >> 3) & 1) * 16;

    float acc[4][4][4];
    #pragma unroll
    for (int mi = 0; mi < 4; mi++)
        #pragma unroll
        for (int nt = 0; nt < 4; nt++)
            #pragma unroll
            for (int e = 0; e < 4; e++) acc[mi][nt][e] = 0.f;

    #pragma unroll
    for (int ks = 0; ks < 16; ks++) {
        uint32_t af[4][4], bf[2][4];
        #pragma unroll
        for (int mi = 0; mi < 4; mi++)
            ldm_x4(af[mi], sA + (uint32_t)(a_row + mi * 16) * 512 +
                           (((uint32_t)(ks * 32 + a_kb)) ^ a_swz));
        #pragma unroll
        for (int nj = 0; nj < 2; nj++)
            ldm_x4(bf[nj], sB + (uint32_t)(b_row + nj * 16) * 512 +
                           (((uint32_t)(ks * 32 + b_kb)) ^ b_swz));
        #pragma unroll
        for (int mi = 0; mi < 4; mi++)
            #pragma unroll
            for (int nt = 0; nt < 4; nt++)
                mma_bf16(acc[mi][nt], af[mi],
                         bf[nt >> 1][(nt & 1) * 2], bf[nt >> 1][(nt & 1) * 2 + 1]);
    }

    __syncthreads();   // operands consumed; reuse smem for scores

    // Scores: sc = cn[k] - 2*S; smem layout [128][132] f32
    #pragma unroll
    for (int mi = 0; mi < 4; mi++) {
        int r0 = wm + mi * 16 + (lane >> 2);
        #pragma unroll
        for (int nt = 0; nt < 4; nt++) {
            int c0 = wn + nt * 8 + (lane & 3) * 2;
            float cn0 = s_cn[c0], cn1 = s_cn[c0 + 1];
            scores[r0 * 132 + c0]           = fmaf(-2.f, acc[mi][nt][0], cn0);
            scores[r0 * 132 + c0 + 1]       = fmaf(-2.f, acc[mi][nt][1], cn1);
            scores[(r0 + 8) * 132 + c0]     = fmaf(-2.f, acc[mi][nt][2], cn0);
            scores[(r0 + 8) * 132 + c0 + 1] = fmaf(-2.f, acc[mi][nt][3], cn1);
        }
    }
    __syncthreads();

    // Scan: 2 threads per pixel row (64 codes each)
    const int row = tid >> 1, half = tid & 1;
    const float* sr = scores + row * 132 + half * 64;
    float best = 3.4e38f;
    #pragma unroll
    for (int q = 0; q < 16; q++) {
        float4 v = *reinterpret_cast<const float4*>(sr + q * 4);
        best = fminf(best, fminf(fminf(v.x, v.y), fminf(v.z, v.w)));
    }
    float ob = __shfl_xor_sync(0xFFFFFFFFu, best, 1);
    best = fminf(best, ob);
    const unsigned pix = (unsigned)(pt * 128 + row);
    if (half == 0) g_tilemin[pix * 8 + kt] = best;
    const float thr = best + EPS_MARGIN;

    // Candidate push: warp-aggregated SMEM counter + staging buffer
    for (int j = 0; j < 64; j++) {
        float sc = sr[j];
        bool pred = (sc <= thr);
        unsigned mask = __ballot_sync(0xFFFFFFFFu, pred);
        if (mask) {
            int leader = __ffs(mask) - 1;
            unsigned widx = 0;
            if (lane == leader) widx = atomicAdd(&s_cnt, (unsigned)__popc(mask));
            widx = __shfl_sync(0xFFFFFFFFu, widx, leader);
            if (pred) {
                unsigned slot = widx + __popc(mask & ((1u << lane) - 1u));
                unsigned k = (unsigned)(kt * 128 + half * 64 + j);
                unsigned long long entry =
                    ((unsigned long long)__float_as_uint(sc) << 32) |
                    ((unsigned long long)pix << 10) | k;
                if (slot < STAGE_CAP) {
                    stage[slot] = entry;
                } else {  // overflow fallback (statistically never)
                    unsigned gs = atomicAdd(&g_ncand, 1u);
                    if (gs < CAND_CAP) g_cand[gs] = entry;
                }
            }
        }
    }
    __syncthreads();

    // One global atomic per CTA, then coalesced flush
    const unsigned total = min(s_cnt, (unsigned)STAGE_CAP);
    if (tid == 0) s_base = atomicAdd(&g_ncand, total);
    __syncthreads();
    const unsigned gbase = s_base;
    for (unsigned i = tid; i < total; i += 256) {
        unsigned dst = gbase + i;
        if (dst < CAND_CAP) g_cand[dst] = stage[i];
    }
}

// ---------------------------------------------------------------------------
// Kernel 2b: per-pixel global min of the 8 tile minima
// ---------------------------------------------------------------------------
__global__ void gmin_kernel() {
    int p = blockIdx.x * blockDim.x + threadIdx.x;
    if (p >= NPIX) return;
    float m = 3.4e38f;
    #pragma unroll
    for (int t = 0; t < 8; t++) m = fminf(m, g_tilemin[p * 8 + t]);
    g_gmin[p] = m;
}

// ---------------------------------------------------------------------------
// Kernel 3: exact fp32 rescore of gated candidates (one warp each).
// Gate: candidate's bf16 score within EPS of pixel's global bf16 min.
// score = fl(fl(A - 2*dot) + cn)  — the Round-2-validated rounding chain.
// ---------------------------------------------------------------------------
__global__ __launch_bounds__(256)
void rescore_kernel(const float* __restrict__ C) {
    const unsigned int count = min(g_ncand, (unsigned)CAND_CAP);
    const int lane = threadIdx.x & 31;
    const unsigned gw = (blockIdx.x * blockDim.x + threadIdx.x) >> 5;
    const unsigned nw = (gridDim.x * blockDim.x) >> 5;

    for (unsigned i = gw; i < count; i += nw) {
        unsigned long long e = g_cand[i];
        float sc_bf = __uint_as_float((unsigned)(e >> 32));
        unsigned low = (unsigned)e;
        unsigned pix = low >> 10, k = low & 1023u;
        if (sc_bf > g_gmin[pix] + EPS_MARGIN) continue;

        const float4* xr = reinterpret_cast<const float4*>(g_Xt + (size_t)pix * D_);
        const float4* cr = reinterpret_cast<const float4*>(C + (size_t)k * D_);
        float dot = 0.f;
        #pragma unroll
        for (int t = 0; t < 2; t++) {
            float4 xv = xr[lane * 2 + t];
            float4 cv = cr[lane * 2 + t];
            dot = fmaf(xv.x, cv.x, dot);
            dot = fmaf(xv.y, cv.y, dot);
            dot = fmaf(xv.z, cv.z, dot);
            dot = fmaf(xv.w, cv.w, dot);
        }
        #pragma unroll
        for (int o = 16; o > 0; o >>= 1) dot += __shfl_down_sync(0xFFFFFFFFu, dot, o);
        if (lane == 0) {
            float sc = __fadd_rn(__fadd_rn(g_A[pix], __fmul_rn(-2.0f, dot)), g_cn[k]);
            unsigned long long key =
                ((unsigned long long)float_to_ordered(sc) << 32) | (unsigned long long)k;
            atomicMin(&g_best[pix], key);
        }
    }
}

// ---------------------------------------------------------------------------
// Kernel 4: gather output (NCHW) + per-block loss partial sums.
// ---------------------------------------------------------------------------
__global__ __launch_bounds__(256)
void gather_kernel(const float* __restrict__ X, const float* __restrict__ C,
                   float* __restrict__ out) {
    __shared__ float red[8];
    const int bd = blockIdx.x;
    const int b  = bd >> 8;
    const int d  = bd & 255;
    const int p  = threadIdx.x * 4;

    const unsigned long long* __restrict__ best = &g_best[b * HW_];
    const size_t base = ((size_t)b * D_ + d) * HW_ + p;

    float4 x = *reinterpret_cast<const float4*>(&X[base]);
    float q[4];
    #pragma unroll
    for (int j = 0; j < 4; j++) {
        int k = (int)(unsigned int)(best[p + j] & 0xFFFFFFFFull);
        q[j] = C[(size_t)k * D_ + d];
    }
    *reinterpret_cast<float4*>(&out[base]) = make_float4(q[0], q[1], q[2], q[3]);

    float dx0 = q[0] - x.x, dx1 = q[1] - x.y, dx2 = q[2] - x.z, dx3 = q[3] - x.w;
    float s = dx0 * dx0 + dx1 * dx1 + dx2 * dx2 + dx3 * dx3;
    #pragma unroll
    for (int o = 16; o > 0; o >>= 1) s += __shfl_down_sync(0xFFFFFFFFu, s, o);
    int warp = threadIdx.x >> 5;
    if ((threadIdx.x & 31) == 0) red[warp] = s;
    __syncthreads();
    if (threadIdx.x == 0) {
        float t = 0.f;
        #pragma unroll
        for (int w = 0; w < 8; w++) t += red[w];
        g_part[bd] = t;
    }
}

// ---------------------------------------------------------------------------
// Kernel 5: final loss reduction
// ---------------------------------------------------------------------------
__global__ void finalize_kernel(float* __restrict__ out, int loss_idx) {
    __shared__ double red[256];
    double s = 0.0;
    for (int i = threadIdx.x; i < B_ * D_; i += 256) s += (double)g_part[i];
    red[threadIdx.x] = s;
    __syncthreads();
    for (int o = 128; o > 0; o >>= 1) {
        if (threadIdx.x < o) red[threadIdx.x] += red[threadIdx.x + o];
        __syncthreads();
    }
    if (threadIdx.x == 0) {
        double mse = red[0] / (double)NELM;
        out[loss_idx] = (float)(1.25 * mse);
    }
}

// ---------------------------------------------------------------------------
extern "C" void kernel_launch(void* const* d_in, const int* in_sizes, int n_in,
                              void* d_out, int out_size) {
    const float* X = (const float*)d_in[0];   // [64,256,32,32] f32 NCHW
    const float* C = (const float*)d_in[1];   // [1024,256] f32
    float* out = (float*)d_out;

    static const int SMEM_BYTES = 131072 + 1024;   // A/B tiles (+ align slack)
    cudaFuncSetAttribute(vq_mma_kernel,
                         cudaFuncAttributeMaxDynamicSharedMemorySize, SMEM_BYTES);

    init_kernel<<<NPIX / 256, 256>>>();
    cn_kernel<<<K_ / 256, 256>>>(C);
    a_kernel<<<B_, 1024>>>(X);
    cbf_kernel<<<(K_ * D_) / 1024, 1024>>>(C);
    transpose_kernel<<<dim3(HW_ / 32, D_ / 32, B_), dim3(32, 8)>>>(X);

    vq_mma_kernel<<<dim3(NPIX / 128, K_ / 128), 256, SMEM_BYTES>>>();

    gmin_kernel<<<NPIX / 256, 256>>>();
    rescore_kernel<<<2048, 256>>>(C);

    gather_kernel<<<B_ * D_, 256>>>(X, C, out);

    if (out_size > NELM) {
        finalize_kernel<<<1, 256>>>(out, out_size - 1);
    }
}

// round 6
// speedup vs baseline: 2.1494x; 1.4131x over previous
#include <cuda_runtime.h>
#include <cuda_bf16.h>
#include <cstdint>

// Problem constants (fixed for this dataset)
#define B_   64
#define D_   256
#define HW_  1024            // 32*32
#define K_   1024            // num embeddings
#define NPIX (B_ * HW_)      // 65536
#define NELM (B_ * D_ * HW_) // 16777216
#define CAND_CAP 1048576
#define EPS_MARGIN 5e-3f
#define STAGE_CAP 3072

// ---------------------------------------------------------------------------
// Scratch (device globals; no cudaMalloc allowed)
// ---------------------------------------------------------------------------
__device__ unsigned long long g_best[NPIX];   // packed (orderable_score<<32)|k
__device__ float g_cn[K_];                    // |c_k|^2 (exact sequential chain)
__device__ float g_A[NPIX];                   // |x_n|^2 (exact sequential chain)
__device__ float g_part[B_ * D_];             // loss partials
__device__ float g_Xt[NPIX * D_];             // X transposed: [pix][d] fp32
__device__ __nv_bfloat16 g_Xt_bf[NPIX * D_];  // bf16 copy
__device__ __nv_bfloat16 g_Cbf[K_ * D_];      // codebook bf16
__device__ unsigned long long g_cand[CAND_CAP]; // (f32score_bits<<32)|(pix<<10)|k
__device__ unsigned int g_ncand;

__device__ __forceinline__ unsigned int float_to_ordered(float f) {
    unsigned int u = __float_as_uint(f);
    return (u & 0x80000000u) ? ~u : (u | 0x80000000u);
}
__device__ __forceinline__ float ordered_to_float(unsigned int o) {
    unsigned int u = (o & 0x80000000u) ? (o & 0x7FFFFFFFu) : ~o;
    return __uint_as_float(u);
}

__device__ __forceinline__ uint32_t smem_u32(const void* p) {
    uint32_t a;
    asm("{ .reg .u64 t; cvta.to.shared.u64 t, %1; cvt.u32.u64 %0, t; }"
        : "=r"(a) : "l"(p));
    return a;
}

// cp.async 16B (sm_80+, legal on plain sm_103 target)
__device__ __forceinline__ void cp16(uint32_t saddr, const void* g) {
    asm volatile("cp.async.cg.shared.global [%0], [%1], 16;"
                 :: "r"(saddr), "l"(g) : "memory");
}

// ldmatrix x4 (non-transposed, b16)
__device__ __forceinline__ void ldm_x4(uint32_t* r, uint32_t addr) {
    asm volatile("ldmatrix.sync.aligned.m8n8.x4.shared.b16 {%0,%1,%2,%3}, [%4];"
                 : "=r"(r[0]), "=r"(r[1]), "=r"(r[2]), "=r"(r[3]) : "r"(addr));
}

// bf16 HMMA m16n8k16, f32 accumulate (sm_80+)
__device__ __forceinline__ void mma_bf16(float* c, const uint32_t* a,
                                         uint32_t b0, uint32_t b1) {
    asm volatile(
        "mma.sync.aligned.m16n8k16.row.col.f32.bf16.bf16.f32 "
        "{%0,%1,%2,%3}, {%4,%5,%6,%7}, {%8,%9}, {%0,%1,%2,%3};"
        : "+f"(c[0]), "+f"(c[1]), "+f"(c[2]), "+f"(c[3])
        : "r"(a[0]), "r"(a[1]), "r"(a[2]), "r"(a[3]), "r"(b0), "r"(b1));
}

// ---------------------------------------------------------------------------
// Kernel 0: init g_best + candidate counter
// ---------------------------------------------------------------------------
__global__ void init_kernel() {
    int i = blockIdx.x * blockDim.x + threadIdx.x;
    if (i < NPIX) g_best[i] = 0xFFFFFFFFFFFFFFFFull;
    if (i == 0) g_ncand = 0;
}

// ---------------------------------------------------------------------------
// Kernel 1: |c_k|^2, exact sequential fp32 chain (validated Round 2)
// ---------------------------------------------------------------------------
__global__ void cn_kernel(const float* __restrict__ C) {
    int k = blockIdx.x * blockDim.x + threadIdx.x;
    if (k >= K_) return;
    const float* row = C + (size_t)k * D_;
    float s = 0.f;
    for (int d = 0; d < D_; d++) s = __fadd_rn(s, __fmul_rn(row[d], row[d]));
    g_cn[k] = s;
}

// ---------------------------------------------------------------------------
// Kernel 1b: |x_p|^2, exact sequential fp32 chain (validated Round 2)
// ---------------------------------------------------------------------------
__global__ __launch_bounds__(1024)
void a_kernel(const float* __restrict__ X) {
    const int b = blockIdx.x;
    const int p = threadIdx.x;
    const float* Xb = X + (size_t)b * D_ * HW_ + p;
    float s = 0.f;
    #pragma unroll 8
    for (int d = 0; d < D_; d++) {
        float v = Xb[(size_t)d * HW_];
        s = __fadd_rn(s, __fmul_rn(v, v));
    }
    g_A[b * HW_ + p] = s;
}

// ---------------------------------------------------------------------------
// Kernel 1c: codebook -> bf16
// ---------------------------------------------------------------------------
__global__ void cbf_kernel(const float* __restrict__ C) {
    int i = blockIdx.x * blockDim.x + threadIdx.x;
    if (i < K_ * D_) g_Cbf[i] = __float2bfloat16(C[i]);
}

// ---------------------------------------------------------------------------
// Kernel 1d: transpose X NCHW [b][d][p] -> pixel-major [pix][d], f32+bf16
// ---------------------------------------------------------------------------
__global__ __launch_bounds__(256)
void transpose_kernel(const float* __restrict__ X) {
    __shared__ float t[32][33];
    const int b  = blockIdx.z;
    const int dB = blockIdx.y * 32;
    const int pB = blockIdx.x * 32;
    const int tx = threadIdx.x;       // 0..31
    const int ty = threadIdx.y;       // 0..7

    const float* src = X + ((size_t)b * D_ + dB) * HW_ + pB;
    #pragma unroll
    for (int i = 0; i < 32; i += 8)
        t[ty + i][tx] = src[(size_t)(ty + i) * HW_ + tx];
    __syncthreads();

    const size_t obase = ((size_t)(b * HW_ + pB)) * D_ + dB;
    #pragma unroll
    for (int i = 0; i < 32; i += 8) {
        int row = ty + i;
        float v = t[tx][row];
        g_Xt[obase + (size_t)row * D_ + tx] = v;
        g_Xt_bf[obase + (size_t)row * D_ + tx] = __float2bfloat16(v);
    }
}

// ---------------------------------------------------------------------------
// Kernel 2: persistent-A bf16 HMMA GEMM. One CTA = 128 pixels x ALL 1024 codes.
// A staged once; B double-buffered with cp.async prefetch overlapping MMA.
// Per-pixel running min kept in smem (ordered-uint atomicMin); candidates
// emitted per k-tile against the running min (superset), re-filtered at the
// end against the FINAL min, then flushed with ONE global atomic per CTA-warp
// group. Eliminates 8x A reloads, tilemin/gmin arrays, and rescore gating.
// ---------------------------------------------------------------------------
__global__ __launch_bounds__(256, 1)
void vq_mma_kernel() {
    extern __shared__ char dsm_raw[];
    __shared__ float s_cn[K_];
    __shared__ unsigned int s_min[128];
    __shared__ unsigned long long stage[STAGE_CAP];
    __shared__ unsigned int s_cnt;

    const int tid = threadIdx.x, lane = tid & 31, wid = tid >> 5;
    const int pt = blockIdx.x;   // 0..511 pixel tiles (128 pixels each)

    const uint32_t s0 = smem_u32(dsm_raw);
    const uint32_t base = (s0 + 1023) & ~1023u;
    const uint32_t sA = base;
    const uint32_t sB0 = base + 65536, sB1 = base + 131072;

    // Preload all code norms + init per-pixel mins
    #pragma unroll
    for (int i = 0; i < 4; i++) s_cn[tid + i * 256] = g_cn[tid + i * 256];
    if (tid < 128) s_min[tid] = 0xFFFFFFFFu;
    if (tid == 0) s_cnt = 0;

    // Stage A (once) + B tile 0
    const __nv_bfloat16* gA = g_Xt_bf + (size_t)pt * 128 * D_;
    #pragma unroll
    for (int i = 0; i < 16; i++) {
        int v = i * 256 + tid;             // 0..4095 16B chunks
        int r = v >> 5, c = v & 31;
        uint32_t off = (uint32_t)(r * 512) + (((uint32_t)c * 16) ^ ((uint32_t)(r & 7) << 4));
        cp16(sA + off, gA + (size_t)v * 8);
        cp16(sB0 + off, g_Cbf + (size_t)v * 8);
    }
    asm volatile("cp.async.commit_group;");

    // Warp tiling: 2 (m) x 4 (n); ldmatrix lane maps
    const int wm = (wid & 1) * 64;
    const int wn = (wid >> 1) * 32;
    const int a_row = wm + (lane & 15);
    const uint32_t a_swz = (uint32_t)((a_row & 7) << 4);
    const int a_kb = (lane >> 4) * 16;
    const int b_row = wn + ((lane & 7) | ((lane & 16) >> 1));
    const uint32_t b_swz = (uint32_t)((b_row & 7) << 4);
    const int b_kb = ((lane >> 3) & 1) * 16;

    const int r0b = wm + (lane >> 2);          // score row base (mi adds 16)
    const int c0b = wn + (lane & 3) * 2;       // score col base (nt adds 8)

    for (int kt = 0; kt < 8; kt++) {
        const uint32_t sBc = (kt & 1) ? sB1 : sB0;
        const uint32_t sBn = (kt & 1) ? sB0 : sB1;

        asm volatile("cp.async.wait_group 0;" ::: "memory");
        __syncthreads();

        // Prefetch next B tile into the alternate buffer
        if (kt + 1 < 8) {
            const __nv_bfloat16* gBn = g_Cbf + (size_t)(kt + 1) * 128 * D_;
            #pragma unroll
            for (int i = 0; i < 16; i++) {
                int v = i * 256 + tid;
                int r = v >> 5, c = v & 31;
                uint32_t off = (uint32_t)(r * 512) +
                               (((uint32_t)c * 16) ^ ((uint32_t)(r & 7) << 4));
                cp16(sBn + off, gBn + (size_t)v * 8);
            }
            asm volatile("cp.async.commit_group;");
        }

        float acc[4][4][4];
        #pragma unroll
        for (int mi = 0; mi < 4; mi++)
            #pragma unroll
            for (int nt = 0; nt < 4; nt++)
                #pragma unroll
                for (int e = 0; e < 4; e++) acc[mi][nt][e] = 0.f;

        #pragma unroll
        for (int ks = 0; ks < 16; ks++) {
            uint32_t af[4][4], bf[2][4];
            #pragma unroll
            for (int mi = 0; mi < 4; mi++)
                ldm_x4(af[mi], sA + (uint32_t)(a_row + mi * 16) * 512 +
                               (((uint32_t)(ks * 32 + a_kb)) ^ a_swz));
            #pragma unroll
            for (int nj = 0; nj < 2; nj++)
                ldm_x4(bf[nj], sBc + (uint32_t)(b_row + nj * 16) * 512 +
                               (((uint32_t)(ks * 32 + b_kb)) ^ b_swz));
            #pragma unroll
            for (int mi = 0; mi < 4; mi++)
                #pragma unroll
                for (int nt = 0; nt < 4; nt++)
                    mma_bf16(acc[mi][nt], af[mi],
                             bf[nt >> 1][(nt & 1) * 2], bf[nt >> 1][(nt & 1) * 2 + 1]);
        }

        // Scores from registers: sc = cn[k] - 2*S. Update per-pixel running min.
        float sc[4][4][4];
        #pragma unroll
        for (int mi = 0; mi < 4; mi++) {
            float m0 = 3.4e38f, m1 = 3.4e38f;
            #pragma unroll
            for (int nt = 0; nt < 4; nt++) {
                int c0 = c0b + nt * 8;
                float cn0 = s_cn[kt * 128 + c0], cn1 = s_cn[kt * 128 + c0 + 1];
                sc[mi][nt][0] = fmaf(-2.f, acc[mi][nt][0], cn0);
                sc[mi][nt][1] = fmaf(-2.f, acc[mi][nt][1], cn1);
                sc[mi][nt][2] = fmaf(-2.f, acc[mi][nt][2], cn0);
                sc[mi][nt][3] = fmaf(-2.f, acc[mi][nt][3], cn1);
                m0 = fminf(m0, fminf(sc[mi][nt][0], sc[mi][nt][1]));
                m1 = fminf(m1, fminf(sc[mi][nt][2], sc[mi][nt][3]));
            }
            // combine the 4 lanes sharing these rows (lane bits 0,1)
            m0 = fminf(m0, __shfl_xor_sync(0xFFFFFFFFu, m0, 1));
            m0 = fminf(m0, __shfl_xor_sync(0xFFFFFFFFu, m0, 2));
            m1 = fminf(m1, __shfl_xor_sync(0xFFFFFFFFu, m1, 1));
            m1 = fminf(m1, __shfl_xor_sync(0xFFFFFFFFu, m1, 2));
            if ((lane & 3) == 0) {
                atomicMin(&s_min[r0b + mi * 16],     float_to_ordered(m0));
                atomicMin(&s_min[r0b + mi * 16 + 8], float_to_ordered(m1));
            }
        }
        __syncthreads();

        // Emit candidates vs running min (superset of final set)
        const unsigned pixb = (unsigned)(pt * 128);
        #pragma unroll
        for (int mi = 0; mi < 4; mi++) {
            int r0 = r0b + mi * 16;
            float thr0 = ordered_to_float(s_min[r0]) + EPS_MARGIN;
            float thr1 = ordered_to_float(s_min[r0 + 8]) + EPS_MARGIN;
            #pragma unroll
            for (int nt = 0; nt < 4; nt++) {
                int c0 = c0b + nt * 8;
                #pragma unroll
                for (int e = 0; e < 4; e++) {
                    float v = sc[mi][nt][e];
                    float thr = (e < 2) ? thr0 : thr1;
                    if (v <= thr) {
                        unsigned row = (unsigned)(r0 + ((e < 2) ? 0 : 8));
                        unsigned k = (unsigned)(kt * 128 + c0 + (e & 1));
                        unsigned long long entry =
                            ((unsigned long long)__float_as_uint(v) << 32) |
                            ((unsigned long long)(pixb + row) << 10) | k;
                        unsigned slot = atomicAdd(&s_cnt, 1u);
                        if (slot < STAGE_CAP) stage[slot] = entry;
                        else {
                            unsigned gs = atomicAdd(&g_ncand, 1u);
                            if (gs < CAND_CAP) g_cand[gs] = entry;
                        }
                    }
                }
            }
        }
        // next iteration's wait_group+syncthreads guards s_min/stage reuse
    }
    __syncthreads();

    // Final flush: keep only entries within EPS of the FINAL per-pixel min
    const unsigned total = min(s_cnt, (unsigned)STAGE_CAP);
    const unsigned rounded = (total + 255u) & ~255u;
    for (unsigned i = tid; i < rounded; i += 256) {
        bool pred = false;
        unsigned long long e = 0;
        if (i < total) {
            e = stage[i];
            float v = __uint_as_float((unsigned)(e >> 32));
            unsigned row = ((unsigned)e >> 10) & 127u;
            pred = (v <= ordered_to_float(s_min[row]) + EPS_MARGIN);
        }
        unsigned mask = __ballot_sync(0xFFFFFFFFu, pred);
        if (mask) {
            int leader = __ffs(mask) - 1;
            unsigned bidx = 0;
            if (lane == leader) bidx = atomicAdd(&g_ncand, (unsigned)__popc(mask));
            bidx = __shfl_sync(0xFFFFFFFFu, bidx, leader);
            if (pred) {
                unsigned dst = bidx + __popc(mask & ((1u << lane) - 1u));
                if (dst < CAND_CAP) g_cand[dst] = e;
            }
        }
    }
}

// ---------------------------------------------------------------------------
// Kernel 3: exact fp32 rescore of candidates (one warp each), no gating.
// score = fl(fl(A - 2*dot) + cn)  — the Round-2-validated rounding chain.
// ---------------------------------------------------------------------------
__global__ __launch_bounds__(256)
void rescore_kernel(const float* __restrict__ C) {
    const unsigned int count = min(g_ncand, (unsigned)CAND_CAP);
    const int lane = threadIdx.x & 31;
    const unsigned gw = (blockIdx.x * blockDim.x + threadIdx.x) >> 5;
    const unsigned nw = (gridDim.x * blockDim.x) >> 5;

    for (unsigned i = gw; i < count; i += nw) {
        unsigned long long e = g_cand[i];
        unsigned low = (unsigned)e;
        unsigned pix = low >> 10, k = low & 1023u;

        const float4* xr = reinterpret_cast<const float4*>(g_Xt + (size_t)pix * D_);
        const float4* cr = reinterpret_cast<const float4*>(C + (size_t)k * D_);
        float dot = 0.f;
        #pragma unroll
        for (int t = 0; t < 2; t++) {
            float4 xv = xr[lane * 2 + t];
            float4 cv = cr[lane * 2 + t];
            dot = fmaf(xv.x, cv.x, dot);
            dot = fmaf(xv.y, cv.y, dot);
            dot = fmaf(xv.z, cv.z, dot);
            dot = fmaf(xv.w, cv.w, dot);
        }
        #pragma unroll
        for (int o = 16; o > 0; o >>= 1) dot += __shfl_down_sync(0xFFFFFFFFu, dot, o);
        if (lane == 0) {
            float sc = __fadd_rn(__fadd_rn(g_A[pix], __fmul_rn(-2.0f, dot)), g_cn[k]);
            unsigned long long key =
                ((unsigned long long)float_to_ordered(sc) << 32) | (unsigned long long)k;
            atomicMin(&g_best[pix], key);
        }
    }
}

// ---------------------------------------------------------------------------
// Kernel 4: gather output (NCHW) + per-block loss partial sums.
// ---------------------------------------------------------------------------
__global__ __launch_bounds__(256)
void gather_kernel(const float* __restrict__ X, const float* __restrict__ C,
                   float* __restrict__ out) {
    __shared__ float red[8];
    const int bd = blockIdx.x;
    const int b  = bd >> 8;
    const int d  = bd & 255;
    const int p  = threadIdx.x * 4;

    const unsigned long long* __restrict__ best = &g_best[b * HW_];
    const size_t base = ((size_t)b * D_ + d) * HW_ + p;

    float4 x = *reinterpret_cast<const float4*>(&X[base]);
    float q[4];
    #pragma unroll
    for (int j = 0; j < 4; j++) {
        int k = (int)(unsigned int)(best[p + j] & 0xFFFFFFFFull);
        q[j] = C[(size_t)k * D_ + d];
    }
    *reinterpret_cast<float4*>(&out[base]) = make_float4(q[0], q[1], q[2], q[3]);

    float dx0 = q[0] - x.x, dx1 = q[1] - x.y, dx2 = q[2] - x.z, dx3 = q[3] - x.w;
    float s = dx0 * dx0 + dx1 * dx1 + dx2 * dx2 + dx3 * dx3;
    #pragma unroll
    for (int o = 16; o > 0; o >>= 1) s += __shfl_down_sync(0xFFFFFFFFu, s, o);
    int warp = threadIdx.x >> 5;
    if ((threadIdx.x & 31) == 0) red[warp] = s;
    __syncthreads();
    if (threadIdx.x == 0) {
        float t = 0.f;
        #pragma unroll
        for (int w = 0; w < 8; w++) t += red[w];
        g_part[bd] = t;
    }
}

// ---------------------------------------------------------------------------
// Kernel 5: final loss reduction
// ---------------------------------------------------------------------------
__global__ void finalize_kernel(float* __restrict__ out, int loss_idx) {
    __shared__ double red[256];
    double s = 0.0;
    for (int i = threadIdx.x; i < B_ * D_; i += 256) s += (double)g_part[i];
    red[threadIdx.x] = s;
    __syncthreads();
    for (int o = 128; o > 0; o >>= 1) {
        if (threadIdx.x < o) red[threadIdx.x] += red[threadIdx.x + o];
        __syncthreads();
    }
    if (threadIdx.x == 0) {
        double mse = red[0] / (double)NELM;
        out[loss_idx] = (float)(1.25 * mse);
    }
}

// ---------------------------------------------------------------------------
extern "C" void kernel_launch(void* const* d_in, const int* in_sizes, int n_in,
                              void* d_out, int out_size) {
    const float* X = (const float*)d_in[0];   // [64,256,32,32] f32 NCHW
    const float* C = (const float*)d_in[1];   // [1024,256] f32
    float* out = (float*)d_out;

    static const int SMEM_BYTES = 196608 + 1024;   // A + 2xB (+ align slack)
    cudaFuncSetAttribute(vq_mma_kernel,
                         cudaFuncAttributeMaxDynamicSharedMemorySize, SMEM_BYTES);

    init_kernel<<<NPIX / 256, 256>>>();
    cn_kernel<<<K_ / 256, 256>>>(C);
    a_kernel<<<B_, 1024>>>(X);
    cbf_kernel<<<(K_ * D_) / 1024, 1024>>>(C);
    transpose_kernel<<<dim3(HW_ / 32, D_ / 32, B_), dim3(32, 8)>>>(X);

    vq_mma_kernel<<<NPIX / 128, 256, SMEM_BYTES>>>();

    rescore_kernel<<<1024, 256>>>(C);

    gather_kernel<<<B_ * D_, 256>>>(X, C, out);

    if (out_size > NELM) {
        finalize_kernel<<<1, 256>>>(out, out_size - 1);
    }
}